// round 5
// baseline (speedup 1.0000x reference)
#include <cuda_runtime.h>
#include <math.h>

#define KB 10
#define VV 50257
#define EE 128
#define H1D 128
#define H2D 64
#define QQ 64
#define TENC 2048
#define MAXLEN 30
#define SOSTOK 1
#define EOSTOK 2
#define NBL 296
#define RPB 170            // 296*170 = 50320 >= 50257
#define NCHUNK 8
#define CHUNK 256
#define SEQW (MAXLEN + 1)  // 31
#define TPB 12             // candidates kept per (beam, block)

// ---------------- persistent device state ----------------
__device__ float g_h1[KB*H1D], g_c1[KB*H1D], g_h2[KB*H2D], g_c2[KB*H2D], g_ctx[KB*QQ];
__device__ float g_h1n[KB*H1D], g_c1n[KB*H1D], g_h2n[KB*H2D], g_c2n[KB*H2D], g_ctxn[KB*QQ];
__device__ float g_scores[KB];
__device__ int   g_prev[KB], g_fin[KB], g_seqs[KB*SEQW];
__device__ double g_attM[KB*NCHUNK], g_attA[KB*NCHUNK], g_attB[KB*NCHUNK];
__device__ double g_attC[KB*NCHUNK*QQ];
__device__ double g_sump[NBL*KB];
__device__ float g_cand_val[NBL*KB*TPB];
__device__ int   g_cand_idx[NBL*KB*TPB];

// order-preserving float -> u32 key (larger key == larger float)
__device__ __forceinline__ unsigned ordkey(float f){
  unsigned u = __float_as_uint(f);
  return (u & 0x80000000u) ? ~u : (u | 0x80000000u);
}
__device__ __forceinline__ float unordkey(unsigned k){
  unsigned u = (k & 0x80000000u) ? (k & 0x7FFFFFFFu) : ~k;
  return __uint_as_float(u);
}
__device__ __forceinline__ double dsig(double x){ return 1.0/(1.0 + exp(-x)); }

// ---------------- init ----------------
__global__ void init_kernel(){
  int t = threadIdx.x;
  for (int i=t;i<KB*H1D;i+=256){ g_h1[i]=0.f; g_c1[i]=0.f; }
  for (int i=t;i<KB*H2D;i+=256){ g_h2[i]=0.f; g_c2[i]=0.f; }
  for (int i=t;i<KB*QQ;i+=256)  g_ctx[i]=0.f;
  for (int i=t;i<KB*SEQW;i+=256) g_seqs[i]=SOSTOK;
  if (t<KB){ g_scores[t]=0.f; g_prev[t]=SOSTOK; g_fin[t]=0; }
}

// ---------------- LSTM1: grid(128), block(128) ----------------
__global__ void lstm1_kernel(const float* __restrict__ emb, const float* __restrict__ Wih,
                             const float* __restrict__ Whh, const float* __restrict__ bih,
                             const float* __restrict__ bhh){
  __shared__ float sx[KB*192], sh[KB*H1D];
  __shared__ double sg[4*KB];
  int t = threadIdx.x, n = blockIdx.x;
  for (int i=t;i<KB*192;i+=128){
    int b=i/192, j=i%192;
    sx[i] = (j<EE) ? emb[(size_t)g_prev[b]*EE + j] : g_ctx[b*QQ + (j-EE)];
  }
  for (int i=t;i<KB*H1D;i+=128) sh[i] = g_h1[i];
  __syncthreads();
  int g = t>>5, lane = t&31;
  const float* wi = Wih + (size_t)(g*H1D+n)*192;
  const float* wh = Whh + (size_t)(g*H1D+n)*H1D;
  for (int b=0;b<KB;b++){
    double s=0.0;
    for (int j=lane;j<192;j+=32)  s += (double)wi[j]*(double)sx[b*192+j];
    for (int j=lane;j<H1D;j+=32)  s += (double)wh[j]*(double)sh[b*H1D+j];
    for (int o=16;o>0;o>>=1) s += __shfl_down_sync(0xffffffffu, s, o);
    if (lane==0) sg[g*KB+b] = s + (double)bih[g*H1D+n] + (double)bhh[g*H1D+n];
  }
  __syncthreads();
  if (t<KB){
    double gi=sg[0*KB+t], gf=sg[1*KB+t], gg=sg[2*KB+t], go=sg[3*KB+t];
    double c = dsig(gf)*(double)g_c1[t*H1D+n] + dsig(gi)*tanh(gg);
    float cf = (float)c;
    g_c1n[t*H1D+n] = cf;
    g_h1n[t*H1D+n] = (float)(dsig(go)*tanh((double)cf));
  }
}

// ---------------- LSTM2: grid(64), block(128) ----------------
__global__ void lstm2_kernel(const float* __restrict__ Wih, const float* __restrict__ Whh,
                             const float* __restrict__ bih, const float* __restrict__ bhh){
  __shared__ float sx[KB*H1D], sh[KB*H2D];
  __shared__ double sg[4*KB];
  int t = threadIdx.x, n = blockIdx.x;
  for (int i=t;i<KB*H1D;i+=128) sx[i] = g_h1n[i];
  for (int i=t;i<KB*H2D;i+=128) sh[i] = g_h2[i];
  __syncthreads();
  int g = t>>5, lane = t&31;
  const float* wi = Wih + (size_t)(g*H2D+n)*H1D;
  const float* wh = Whh + (size_t)(g*H2D+n)*H2D;
  for (int b=0;b<KB;b++){
    double s=0.0;
    for (int j=lane;j<H1D;j+=32) s += (double)wi[j]*(double)sx[b*H1D+j];
    for (int j=lane;j<H2D;j+=32) s += (double)wh[j]*(double)sh[b*H2D+j];
    for (int o=16;o>0;o>>=1) s += __shfl_down_sync(0xffffffffu, s, o);
    if (lane==0) sg[g*KB+b] = s + (double)bih[g*H2D+n] + (double)bhh[g*H2D+n];
  }
  __syncthreads();
  if (t<KB){
    double gi=sg[0*KB+t], gf=sg[1*KB+t], gg=sg[2*KB+t], go=sg[3*KB+t];
    double c = dsig(gf)*(double)g_c2[t*H2D+n] + dsig(gi)*tanh(gg);
    float cf = (float)c;
    g_c2n[t*H2D+n] = cf;
    g_h2n[t*H2D+n] = (float)(dsig(go)*tanh((double)cf));
  }
}

// ---------------- attention partials (double): grid(80), block(256) ----------------
__global__ void attn_kernel(const float* __restrict__ key, const float* __restrict__ val,
                            const float* __restrict__ mask, const float* __restrict__ Wq,
                            const float* __restrict__ bq){
  __shared__ float h2s[H2D];
  __shared__ double qs[QQ], red[CHUNK], ws[CHUNK], cs[4][QQ];
  int t = threadIdx.x;
  int beam = blockIdx.x / NCHUNK, ch = blockIdx.x % NCHUNK;
  if (t<H2D) h2s[t] = g_h2n[beam*H2D+t];
  __syncthreads();
  if (t<QQ){
    double s = (double)bq[t];
    const float* w = Wq + t*H2D;
    for (int j=0;j<H2D;j++) s += (double)w[j]*(double)h2s[j];
    qs[t]=s;
  }
  __syncthreads();
  int tt = ch*CHUNK + t;
  double e = 0.0;
  const float* kr = key + (size_t)tt*QQ;
  for (int j=0;j<QQ;j++) e += qs[j]*(double)kr[j];
  red[t] = e; __syncthreads();
  for (int o=128;o>0;o>>=1){ if (t<o) red[t]=fmax(red[t],red[t+o]); __syncthreads(); }
  double M = red[0]; __syncthreads();
  double w = exp(e - M);
  double mm = (double)mask[tt];
  ws[t] = w*mm;
  red[t] = w; __syncthreads();
  for (int o=128;o>0;o>>=1){ if (t<o) red[t]+=red[t+o]; __syncthreads(); }
  double A = red[0]; __syncthreads();
  red[t] = w*mm; __syncthreads();
  for (int o=128;o>0;o>>=1){ if (t<o) red[t]+=red[t+o]; __syncthreads(); }
  double B = red[0]; __syncthreads();
  // weighted-value partial: C[v] = sum over this chunk of ws[t]*val[t][v]
  int gg = t>>6, v = t&63;
  double cp = 0.0;
  int base = ch*CHUNK + gg*64;
  for (int tl=0; tl<64; tl++) cp += ws[gg*64+tl]*(double)val[(size_t)(base+tl)*QQ + v];
  cs[gg][v] = cp; __syncthreads();
  if (t<QQ) g_attC[(beam*NCHUNK+ch)*QQ + t] = cs[0][t]+cs[1][t]+cs[2][t]+cs[3][t];
  if (t==0){
    g_attM[beam*NCHUNK+ch]=M; g_attA[beam*NCHUNK+ch]=A; g_attB[beam*NCHUNK+ch]=B;
  }
}

// ---------------- logits + sumexp + per-(beam,block) exact top-12: grid(296), block(256) ----------------
__global__ void logits_kernel(const float* __restrict__ Wc, const float* __restrict__ bc){
  __shared__ __align__(16) float xs[KB*128];
  __shared__ float lg[KB][RPB];
  __shared__ double scf[KB][NCHUNK];
  __shared__ double sAB[KB][2];
  __shared__ double wred[8][KB];
  int t = threadIdx.x;
  if (t < KB){
    double M = -1e300;
    for (int c=0;c<NCHUNK;c++) M = fmax(M, g_attM[t*NCHUNK+c]);
    double A=0.0, B=0.0;
    for (int c=0;c<NCHUNK;c++){
      double s = exp(g_attM[t*NCHUNK+c]-M);
      scf[t][c]=s;
      A += g_attA[t*NCHUNK+c]*s;
      B += g_attB[t*NCHUNK+c]*s;
    }
    sAB[t][0]=A; sAB[t][1]=B;
  }
  __syncthreads();
  // x = concat(h2, ctx) per beam; block 0 persists ctx for the gather
  for (int i=t;i<KB*128;i+=256){
    int b=i>>7, j=i&127;
    float x;
    if (j < H2D) x = g_h2n[b*H2D+j];
    else {
      int v = j - H2D;
      double C = 0.0;
      for (int c=0;c<NCHUNK;c++) C += g_attC[(b*NCHUNK+c)*QQ+v]*scf[b][c];
      double A = sAB[b][0], B = sAB[b][1];
      x = (float)((C/A) / fmax(B/A, 2e-30));
      if (blockIdx.x == 0) g_ctxn[b*QQ+v] = x;
    }
    xs[i] = x;
  }
  __syncthreads();
  // one row per thread
  double ex[KB];
  #pragma unroll
  for (int b=0;b<KB;b++) ex[b]=0.0;
  int r = t;
  int v = blockIdx.x*RPB + r;
  if (r < RPB){
    if (v < VV){
      const float4* wr = (const float4*)(Wc + (size_t)v*128);
      const float4* x4 = (const float4*)xs;
      float acc0[KB], acc1[KB];
      #pragma unroll
      for (int b=0;b<KB;b++){ acc0[b]=0.f; acc1[b]=0.f; }
      #pragma unroll 4
      for (int j=0;j<32;j++){
        float4 wv = wr[j];
        #pragma unroll
        for (int b=0;b<KB;b++){
          float4 xv = x4[b*32+j];
          acc0[b] += wv.x*xv.x + wv.y*xv.y;
          acc1[b] += wv.z*xv.z + wv.w*xv.w;
        }
      }
      double bd = (double)bc[v];
      #pragma unroll
      for (int b=0;b<KB;b++){
        float l = (float)((double)acc0[b] + (double)acc1[b] + bd);
        lg[b][r] = l;
        ex[b] = exp((double)l);
      }
    } else {
      #pragma unroll
      for (int b=0;b<KB;b++) lg[b][r] = -1e30f;
    }
  }
  // block-reduce sumexp per beam (double)
  int wid = t>>5, lane = t&31;
  #pragma unroll
  for (int b=0;b<KB;b++){
    double s = ex[b];
    for (int o=16;o>0;o>>=1) s += __shfl_down_sync(0xffffffffu, s, o);
    if (lane==0) wred[wid][b] = s;
  }
  __syncthreads();
  if (t<KB){
    double s=0.0;
    for (int w=0;w<8;w++) s += wred[w][t];
    g_sump[blockIdx.x*KB+t] = s;
  }
  // per-(beam,block) exact top-12 (warp w handles beams w, w+8)
  for (int bm=wid; bm<KB; bm+=8){
    for (int j=0;j<TPB;j++){
      unsigned long long best=0ull;
      for (int r2=lane; r2<RPB; r2+=32){
        unsigned long long k = ((unsigned long long)ordkey(lg[bm][r2])<<32) | (unsigned)(~(unsigned)r2);
        if (k>best) best=k;
      }
      for (int o=16;o>0;o>>=1){
        unsigned long long ok = __shfl_down_sync(0xffffffffu, best, o);
        if (ok>best) best=ok;
      }
      best = __shfl_sync(0xffffffffu, best, 0);
      int rs = (int)(~(unsigned)(best & 0xffffffffu));
      if (lane==0){
        g_cand_val[(blockIdx.x*KB+bm)*TPB+j] = lg[bm][rs];
        g_cand_idx[(blockIdx.x*KB+bm)*TPB+j] = blockIdx.x*RPB + rs;
        lg[bm][rs] = -1e30f;
      }
      __syncwarp();
    }
  }
}

// ---------------- select top-10 over all candidates + beam gather: 1 block, 256 threads ----------------
__global__ void select_kernel(int step){
  __shared__ float slse[KB], sscore[KB], sval[KB];
  __shared__ int sfin[KB], spb[KB], stok[KB];
  __shared__ unsigned long long skeys[256*10];
  __shared__ unsigned long long rk[256];
  __shared__ unsigned long long topk[KB];
  __shared__ int sseq[KB*SEQW];
  int t = threadIdx.x;
  if (t<KB){
    double s=0.0;
    for (int b2=0;b2<NBL;b2++) s += g_sump[b2*KB+t];
    slse[t] = (float)log(s);
    sscore[t] = g_scores[t];
    sfin[t] = g_fin[t];
  }
  __syncthreads();
  unsigned long long list[10];
  #pragma unroll
  for (int j=0;j<10;j++) list[j]=0ull;
  const int NC = NBL*KB*TPB;
  for (int c=t;c<NC;c+=256){
    int b = (c/TPB)%KB;
    if (sfin[b]) continue;
    if (step==0 && b>0) continue;
    // mirror reference fp32 op order: cand = scores + (logit - lse)
    float logp = g_cand_val[c] - slse[b];
    float v = sscore[b] + logp;
    int flat = b*VV + g_cand_idx[c];
    unsigned long long k = ((unsigned long long)ordkey(v)<<32) | (unsigned)(~(unsigned)flat);
    if (k > list[9]){
      list[9]=k;
      for (int j=8;j>=0;j--){
        if (list[j] < list[j+1]){ unsigned long long tmp=list[j]; list[j]=list[j+1]; list[j+1]=tmp; }
        else break;
      }
    }
  }
  // synthetic EOS candidate for finished beams (logp forced to 0 at <eos>)
  if (t<KB && sfin[t]){
    float v = sscore[t];
    int flat = t*VV + EOSTOK;
    unsigned long long k = ((unsigned long long)ordkey(v)<<32) | (unsigned)(~(unsigned)flat);
    if (k > list[9]){
      list[9]=k;
      for (int j=8;j>=0;j--){
        if (list[j] < list[j+1]){ unsigned long long tmp=list[j]; list[j]=list[j+1]; list[j+1]=tmp; }
        else break;
      }
    }
  }
  for (int j=0;j<10;j++) skeys[t*10+j]=list[j];
  __syncthreads();
  for (int j=0;j<10;j++){
    unsigned long long m=0ull;
    for (int q=0;q<10;q++){ unsigned long long k=skeys[t*10+q]; if (k>m) m=k; }
    rk[t]=m; __syncthreads();
    for (int o=128;o>0;o>>=1){ if (t<o){ if (rk[t+o]>rk[t]) rk[t]=rk[t+o]; } __syncthreads(); }
    unsigned long long win = rk[0];
    if (t==0) topk[j]=win;
    __syncthreads();
    for (int q=0;q<10;q++) if (skeys[t*10+q]==win) skeys[t*10+q]=0ull;
    __syncthreads();
  }
  if (t<KB){
    unsigned long long k = topk[t];
    sval[t] = unordkey((unsigned)(k>>32));
    int flat = (int)(~(unsigned)(k & 0xffffffffu));
    spb[t]  = flat / VV;
    stok[t] = flat % VV;
  }
  for (int i=t;i<KB*SEQW;i+=256) sseq[i] = g_seqs[i];
  __syncthreads();
  for (int i=t;i<KB*H1D;i+=256){
    int nb=i>>7, u=i&127;
    g_h1[i]=g_h1n[spb[nb]*H1D+u];
    g_c1[i]=g_c1n[spb[nb]*H1D+u];
  }
  for (int i=t;i<KB*H2D;i+=256){
    int nb=i>>6, u=i&63;
    g_h2[i]=g_h2n[spb[nb]*H2D+u];
    g_c2[i]=g_c2n[spb[nb]*H2D+u];
    g_ctx[i]=g_ctxn[spb[nb]*QQ+u];
  }
  for (int i=t;i<KB*SEQW;i+=256){
    int nb=i/SEQW, cc=i%SEQW;
    g_seqs[i] = sseq[spb[nb]*SEQW+cc];
  }
  __syncthreads();
  if (t<KB){
    g_seqs[t*SEQW + step + 1] = stok[t];
    g_prev[t]   = stok[t];
    g_scores[t] = sval[t];
    g_fin[t]    = sfin[spb[t]] | (stok[t]==EOSTOK);
  }
}

// ---------------- finalize: seqs (as float), scores, norm_scores ----------------
__global__ void finalize_kernel(float* __restrict__ out){
  __shared__ float snorm[KB];
  int t = threadIdx.x;
  if (t<KB){
    int first=-1;
    for (int c=1;c<=MAXLEN;c++){
      if (g_seqs[t*SEQW+c]==EOSTOK){ first=c-1; break; }
    }
    float len = (first>=0) ? (float)(first+2) : (float)(MAXLEN+2);
    snorm[t] = (float)((double)g_scores[t] / pow((double)len, 1.2));
  }
  __syncthreads();
  for (int i=t;i<KB*SEQW;i+=256) out[i] = (float)g_seqs[i];
  if (t<KB){
    out[KB*SEQW + t]       = g_scores[t];
    out[KB*SEQW + KB + t]  = snorm[t];
  }
}

extern "C" void kernel_launch(void* const* d_in, const int* in_sizes, int n_in,
                              void* d_out, int out_size){
  const float* enc_key = (const float*)d_in[0];
  const float* enc_val = (const float*)d_in[1];
  const float* mask    = (const float*)d_in[2];
  const float* emb     = (const float*)d_in[3];
  const float* Wih1    = (const float*)d_in[4];
  const float* Whh1    = (const float*)d_in[5];
  const float* bih1    = (const float*)d_in[6];
  const float* bhh1    = (const float*)d_in[7];
  const float* Wih2    = (const float*)d_in[8];
  const float* Whh2    = (const float*)d_in[9];
  const float* bih2    = (const float*)d_in[10];
  const float* bhh2    = (const float*)d_in[11];
  const float* Wq      = (const float*)d_in[12];
  const float* bq      = (const float*)d_in[13];
  const float* Wc      = (const float*)d_in[14];
  const float* bc      = (const float*)d_in[15];

  init_kernel<<<1,256>>>();
  for (int step=0; step<MAXLEN; step++){
    lstm1_kernel<<<H1D,128>>>(emb, Wih1, Whh1, bih1, bhh1);
    lstm2_kernel<<<H2D,128>>>(Wih2, Whh2, bih2, bhh2);
    attn_kernel<<<KB*NCHUNK,CHUNK>>>(enc_key, enc_val, mask, Wq, bq);
    logits_kernel<<<NBL,256>>>(Wc, bc);
    select_kernel<<<1,256>>>(step);
  }
  finalize_kernel<<<1,256>>>((float*)d_out);
}

// round 6
// speedup vs baseline: 1.1767x; 1.1767x over previous
#include <cuda_runtime.h>
#include <math.h>

#define KB 10
#define VV 50257
#define EE 128
#define H1D 128
#define H2D 64
#define QQ 64
#define TENC 2048
#define MAXLEN 30
#define SOSTOK 1
#define EOSTOK 2
#define NBL 296
#define RPB 170            // 296*170 = 50320 >= 50257
#define NCHUNK 16
#define CHUNK 128
#define SEQW (MAXLEN + 1)  // 31
#define TPB 12             // candidates kept per (beam, block)

// ---------------- persistent device state ----------------
__device__ float g_h1[KB*H1D], g_c1[KB*H1D], g_h2[KB*H2D], g_c2[KB*H2D], g_ctx[KB*QQ];
__device__ float g_h1n[KB*H1D], g_c1n[KB*H1D], g_h2n[KB*H2D], g_c2n[KB*H2D], g_ctxn[KB*QQ];
__device__ float g_scores[KB];
__device__ int   g_prev[KB], g_fin[KB], g_seqs[KB*SEQW];
__device__ double g_attM[KB*NCHUNK], g_attA[KB*NCHUNK], g_attB[KB*NCHUNK];
__device__ double g_attC[KB*NCHUNK*QQ];
__device__ double g_sump[NBL*KB];
__device__ float g_cand_val[NBL*KB*TPB];
__device__ int   g_cand_idx[NBL*KB*TPB];

// order-preserving float -> u32 key (larger key == larger float)
__device__ __forceinline__ unsigned ordkey(float f){
  unsigned u = __float_as_uint(f);
  return (u & 0x80000000u) ? ~u : (u | 0x80000000u);
}
__device__ __forceinline__ float unordkey(unsigned k){
  unsigned u = (k & 0x80000000u) ? (k & 0x7FFFFFFFu) : ~k;
  return __uint_as_float(u);
}
// packed 2xfp32 FMA: d.lo += a.lo*b.lo ; d.hi += a.hi*b.hi
__device__ __forceinline__ void ffma2(unsigned long long& d, unsigned long long a, unsigned long long b){
  asm("fma.rn.f32x2 %0, %1, %2, %0;" : "+l"(d) : "l"(a), "l"(b));
}

// ---------------- init ----------------
__global__ void init_kernel(){
  int t = threadIdx.x;
  for (int i=t;i<KB*H1D;i+=256){ g_h1[i]=0.f; g_c1[i]=0.f; }
  for (int i=t;i<KB*H2D;i+=256){ g_h2[i]=0.f; g_c2[i]=0.f; }
  for (int i=t;i<KB*QQ;i+=256)  g_ctx[i]=0.f;
  for (int i=t;i<KB*SEQW;i+=256) g_seqs[i]=SOSTOK;
  if (t<KB){ g_scores[t]=0.f; g_prev[t]=SOSTOK; g_fin[t]=0; }
}

// ---------------- LSTM1: grid(128), block(128) ----------------
__global__ void lstm1_kernel(const float* __restrict__ emb, const float* __restrict__ Wih,
                             const float* __restrict__ Whh, const float* __restrict__ bih,
                             const float* __restrict__ bhh){
  __shared__ float sx[KB*192], sh[KB*H1D];
  __shared__ double sg[4*KB], snl[4*KB];
  int t = threadIdx.x, n = blockIdx.x;
  for (int i=t;i<KB*192;i+=128){
    int b=i/192, j=i%192;
    sx[i] = (j<EE) ? emb[(size_t)g_prev[b]*EE + j] : g_ctx[b*QQ + (j-EE)];
  }
  for (int i=t;i<KB*H1D;i+=128) sh[i] = g_h1[i];
  __syncthreads();
  int g = t>>5, lane = t&31;
  const float* wi = Wih + (size_t)(g*H1D+n)*192;
  const float* wh = Whh + (size_t)(g*H1D+n)*H1D;
  double s[KB];
  #pragma unroll
  for (int b=0;b<KB;b++) s[b]=0.0;
  for (int j=lane;j<192;j+=32){
    double w = (double)wi[j];
    #pragma unroll
    for (int b=0;b<KB;b++) s[b] += w*(double)sx[b*192+j];
  }
  for (int j=lane;j<H1D;j+=32){
    double w = (double)wh[j];
    #pragma unroll
    for (int b=0;b<KB;b++) s[b] += w*(double)sh[b*H1D+j];
  }
  #pragma unroll
  for (int b=0;b<KB;b++){
    double v=s[b];
    for (int o=16;o>0;o>>=1) v += __shfl_down_sync(0xffffffffu, v, o);
    s[b]=v;
  }
  if (lane==0){
    double bb = (double)bih[g*H1D+n] + (double)bhh[g*H1D+n];
    #pragma unroll
    for (int b=0;b<KB;b++) sg[g*KB+b] = s[b] + bb;
  }
  __syncthreads();
  if (t<4*KB){
    int gg=t/KB;
    double v = sg[t];
    snl[t] = (gg==2) ? tanh(v) : 1.0/(1.0+exp(-v));
  }
  __syncthreads();
  if (t<KB){
    double c = snl[1*KB+t]*(double)g_c1[t*H1D+n] + snl[0*KB+t]*snl[2*KB+t];
    float cf = (float)c;
    g_c1n[t*H1D+n] = cf;
    g_h1n[t*H1D+n] = (float)(snl[3*KB+t]*tanh((double)cf));
  }
}

// ---------------- LSTM2: grid(64), block(128) ----------------
__global__ void lstm2_kernel(const float* __restrict__ Wih, const float* __restrict__ Whh,
                             const float* __restrict__ bih, const float* __restrict__ bhh){
  __shared__ float sx[KB*H1D], sh[KB*H2D];
  __shared__ double sg[4*KB], snl[4*KB];
  int t = threadIdx.x, n = blockIdx.x;
  for (int i=t;i<KB*H1D;i+=128) sx[i] = g_h1n[i];
  for (int i=t;i<KB*H2D;i+=128) sh[i] = g_h2[i];
  __syncthreads();
  int g = t>>5, lane = t&31;
  const float* wi = Wih + (size_t)(g*H2D+n)*H1D;
  const float* wh = Whh + (size_t)(g*H2D+n)*H2D;
  double s[KB];
  #pragma unroll
  for (int b=0;b<KB;b++) s[b]=0.0;
  for (int j=lane;j<H1D;j+=32){
    double w = (double)wi[j];
    #pragma unroll
    for (int b=0;b<KB;b++) s[b] += w*(double)sx[b*H1D+j];
  }
  for (int j=lane;j<H2D;j+=32){
    double w = (double)wh[j];
    #pragma unroll
    for (int b=0;b<KB;b++) s[b] += w*(double)sh[b*H2D+j];
  }
  #pragma unroll
  for (int b=0;b<KB;b++){
    double v=s[b];
    for (int o=16;o>0;o>>=1) v += __shfl_down_sync(0xffffffffu, v, o);
    s[b]=v;
  }
  if (lane==0){
    double bb = (double)bih[g*H2D+n] + (double)bhh[g*H2D+n];
    #pragma unroll
    for (int b=0;b<KB;b++) sg[g*KB+b] = s[b] + bb;
  }
  __syncthreads();
  if (t<4*KB){
    int gg=t/KB;
    double v = sg[t];
    snl[t] = (gg==2) ? tanh(v) : 1.0/(1.0+exp(-v));
  }
  __syncthreads();
  if (t<KB){
    double c = snl[1*KB+t]*(double)g_c2[t*H2D+n] + snl[0*KB+t]*snl[2*KB+t];
    float cf = (float)c;
    g_c2n[t*H2D+n] = cf;
    g_h2n[t*H2D+n] = (float)(snl[3*KB+t]*tanh((double)cf));
  }
}

// ---------------- attention partials (double): grid(KB*16), block(256) ----------------
__global__ void attn_kernel(const float* __restrict__ key, const float* __restrict__ val,
                            const float* __restrict__ mask, const float* __restrict__ Wq,
                            const float* __restrict__ bq){
  __shared__ float h2s[H2D];
  __shared__ double qp[4][QQ];
  __shared__ double qs[QQ];
  __shared__ double ws[CHUNK];
  __shared__ double redm[4];
  __shared__ double redab[4][2];
  __shared__ double cs4[4][QQ];
  int t = threadIdx.x;
  int beam = blockIdx.x >> 4, ch = blockIdx.x & 15;
  if (t<H2D) h2s[t] = g_h2n[beam*H2D+t];
  __syncthreads();
  {
    int qi = t&63, part = t>>6;  // 4 partials of 16
    const float* w = Wq + qi*H2D + part*16;
    double s=0.0;
    #pragma unroll
    for (int j=0;j<16;j++) s += (double)w[j]*(double)h2s[part*16+j];
    qp[part][qi]=s;
  }
  __syncthreads();
  if (t<QQ) qs[t] = (double)bq[t] + qp[0][t]+qp[1][t]+qp[2][t]+qp[3][t];
  __syncthreads();
  int lane = t&31, wid = t>>5;
  int tt = ch*CHUNK + (t&127);
  double e = -1e300;
  if (t<128){
    const float4* kr = (const float4*)(key + (size_t)tt*QQ);
    double e0=0,e1=0,e2=0,e3=0;
    #pragma unroll
    for (int j=0;j<16;j++){
      float4 kv = kr[j];
      e0 += qs[4*j+0]*(double)kv.x;
      e1 += qs[4*j+1]*(double)kv.y;
      e2 += qs[4*j+2]*(double)kv.z;
      e3 += qs[4*j+3]*(double)kv.w;
    }
    e = (e0+e1)+(e2+e3);
  }
  // max over 128 tokens (warps 0-3)
  double m = e;
  for (int o=16;o>0;o>>=1) m = fmax(m, __shfl_down_sync(0xffffffffu, m, o));
  if (lane==0 && wid<4) redm[wid]=m;
  __syncthreads();
  double M = fmax(fmax(redm[0],redm[1]),fmax(redm[2],redm[3]));
  double wexp=0.0, wmask=0.0;
  if (t<128){
    wexp = exp(e-M);
    wmask = wexp*(double)mask[tt];
    ws[t&127] = wmask;
  }
  double a=wexp, b2=wmask;
  for (int o=16;o>0;o>>=1){
    a  += __shfl_down_sync(0xffffffffu, a, o);
    b2 += __shfl_down_sync(0xffffffffu, b2, o);
  }
  if (lane==0 && wid<4){ redab[wid][0]=a; redab[wid][1]=b2; }
  __syncthreads();
  // ctx partial: 4 groups of 32 tokens each, v = t&63
  {
    int v = t&63, grp = t>>6;
    int base = grp*32;
    double c0=0.0, c1=0.0;
    const float* vb = val + (size_t)(ch*CHUNK+base)*QQ + v;
    #pragma unroll 4
    for (int tl=0; tl<32; tl+=2){
      c0 += ws[base+tl]  *(double)vb[(size_t)tl*QQ];
      c1 += ws[base+tl+1]*(double)vb[(size_t)(tl+1)*QQ];
    }
    cs4[grp][v] = c0+c1;
  }
  __syncthreads();
  if (t<QQ) g_attC[(beam*NCHUNK+ch)*QQ + t] = (cs4[0][t]+cs4[1][t])+(cs4[2][t]+cs4[3][t]);
  if (t==0){
    g_attM[beam*NCHUNK+ch]=M;
    g_attA[beam*NCHUNK+ch]=(redab[0][0]+redab[1][0])+(redab[2][0]+redab[3][0]);
    g_attB[beam*NCHUNK+ch]=(redab[0][1]+redab[1][1])+(redab[2][1]+redab[3][1]);
  }
}

// ---------------- logits + sumexp + per-(beam,block) exact top-12: grid(296), block(256) ----------------
__global__ void logits_kernel(const float* __restrict__ Wc, const float* __restrict__ bc){
  __shared__ __align__(16) float xs[KB*128];
  __shared__ float lg[KB][RPB];
  __shared__ double scf[KB][NCHUNK];
  __shared__ double sAB[KB][2];
  __shared__ double sM[KB];
  __shared__ double wred[8][KB];
  int t = threadIdx.x;
  if (t < KB){
    double M = -1e300;
    #pragma unroll
    for (int c=0;c<NCHUNK;c++) M = fmax(M, g_attM[t*NCHUNK+c]);
    sM[t]=M;
  }
  __syncthreads();
  if (t < KB*NCHUNK){
    int b=t/NCHUNK, c=t%NCHUNK;
    scf[b][c] = exp(g_attM[b*NCHUNK+c]-sM[b]);
  }
  __syncthreads();
  if (t < KB){
    double A=0.0, B=0.0;
    #pragma unroll
    for (int c=0;c<NCHUNK;c++){
      A += g_attA[t*NCHUNK+c]*scf[t][c];
      B += g_attB[t*NCHUNK+c]*scf[t][c];
    }
    sAB[t][0]=A; sAB[t][1]=B;
  }
  __syncthreads();
  // x = concat(h2, ctx) per beam; block 0 persists ctx for the gather
  for (int i=t;i<KB*128;i+=256){
    int b=i>>7, j=i&127;
    float x;
    if (j < H2D) x = g_h2n[b*H2D+j];
    else {
      int v = j - H2D;
      double C = 0.0;
      #pragma unroll
      for (int c=0;c<NCHUNK;c++) C += g_attC[(b*NCHUNK+c)*QQ+v]*scf[b][c];
      double A = sAB[b][0], B = sAB[b][1];
      x = (float)((C/A) / fmax(B/A, 2e-30));
      if (blockIdx.x == 0) g_ctxn[b*QQ+v] = x;
    }
    xs[i] = x;
  }
  __syncthreads();
  // one row per thread; f32x2-packed GEMV over the j (feature) dimension
  double ex[KB];
  #pragma unroll
  for (int b=0;b<KB;b++) ex[b]=0.0;
  int r = t;
  int v = blockIdx.x*RPB + r;
  if (r < RPB){
    if (v < VV){
      const ulonglong2* wr = (const ulonglong2*)(Wc + (size_t)v*128);
      const ulonglong2* xp = (const ulonglong2*)xs;
      unsigned long long acc[KB];
      #pragma unroll
      for (int b=0;b<KB;b++) acc[b]=0ull;
      #pragma unroll 4
      for (int j=0;j<32;j++){
        ulonglong2 wv = wr[j];
        #pragma unroll
        for (int b=0;b<KB;b++){
          ulonglong2 xv = xp[b*32+j];
          ffma2(acc[b], wv.x, xv.x);
          ffma2(acc[b], wv.y, xv.y);
        }
      }
      double bd = (double)bc[v];
      #pragma unroll
      for (int b=0;b<KB;b++){
        float lo = __uint_as_float((unsigned)(acc[b] & 0xffffffffu));
        float hi = __uint_as_float((unsigned)(acc[b] >> 32));
        float l = (float)((double)lo + (double)hi + bd);
        lg[b][r] = l;
        ex[b] = (double)expf(l);
      }
    } else {
      #pragma unroll
      for (int b=0;b<KB;b++) lg[b][r] = -1e30f;
    }
  }
  // block-reduce sumexp per beam (double)
  int wid = t>>5, lane = t&31;
  #pragma unroll
  for (int b=0;b<KB;b++){
    double s = ex[b];
    for (int o=16;o>0;o>>=1) s += __shfl_down_sync(0xffffffffu, s, o);
    if (lane==0) wred[wid][b] = s;
  }
  __syncthreads();
  if (t<KB){
    double s=0.0;
    for (int w=0;w<8;w++) s += wred[w][t];
    g_sump[blockIdx.x*KB+t] = s;
  }
  // per-(beam,block) exact top-12 (warp w handles beams w, w+8)
  for (int bm=wid; bm<KB; bm+=8){
    for (int j=0;j<TPB;j++){
      unsigned long long best=0ull;
      for (int r2=lane; r2<RPB; r2+=32){
        unsigned long long k = ((unsigned long long)ordkey(lg[bm][r2])<<32) | (unsigned)(~(unsigned)r2);
        if (k>best) best=k;
      }
      for (int o=16;o>0;o>>=1){
        unsigned long long ok = __shfl_down_sync(0xffffffffu, best, o);
        if (ok>best) best=ok;
      }
      best = __shfl_sync(0xffffffffu, best, 0);
      int rs = (int)(~(unsigned)(best & 0xffffffffu));
      if (lane==0){
        g_cand_val[(blockIdx.x*KB+bm)*TPB+j] = lg[bm][rs];
        g_cand_idx[(blockIdx.x*KB+bm)*TPB+j] = blockIdx.x*RPB + rs;
        lg[bm][rs] = -1e30f;
      }
      __syncwarp();
    }
  }
}

// ---------------- select top-10 over all candidates + beam gather: 1 block, 256 threads ----------------
__global__ void select_kernel(int step){
  __shared__ float slse[KB], sscore[KB], sval[KB];
  __shared__ int sfin[KB], spb[KB], stok[KB];
  __shared__ double sp[256];
  __shared__ unsigned long long skeys[256*10];
  __shared__ unsigned long long wmax[8];
  __shared__ unsigned long long swin;
  __shared__ unsigned long long topk[KB];
  __shared__ int sseq[KB*SEQW];
  int t = threadIdx.x, lane = t&31, wid = t>>5;
  // parallel lse: 250 threads, 25 partials per beam
  {
    double s=0.0;
    if (t < 250){
      int b = t/25, part = t%25;
      for (int b2=part; b2<NBL; b2+=25) s += g_sump[b2*KB+b];
    }
    sp[t]=s;
  }
  __syncthreads();
  if (t<KB){
    double s=0.0;
    for (int q=0;q<25;q++) s += sp[t*25+q];
    slse[t] = (float)log(s);
    sscore[t] = g_scores[t];
    sfin[t] = g_fin[t];
  }
  __syncthreads();
  unsigned long long list[10];
  #pragma unroll
  for (int j=0;j<10;j++) list[j]=0ull;
  const int NC = NBL*KB*TPB;
  for (int c=t;c<NC;c+=256){
    int b = (c/TPB)%KB;
    if (sfin[b]) continue;
    if (step==0 && b>0) continue;
    // mirror reference fp32 op order: cand = scores + (logit - lse)
    float logp = g_cand_val[c] - slse[b];
    float v = sscore[b] + logp;
    int flat = b*VV + g_cand_idx[c];
    unsigned long long k = ((unsigned long long)ordkey(v)<<32) | (unsigned)(~(unsigned)flat);
    if (k > list[9]){
      list[9]=k;
      for (int j=8;j>=0;j--){
        if (list[j] < list[j+1]){ unsigned long long tmp=list[j]; list[j]=list[j+1]; list[j+1]=tmp; }
        else break;
      }
    }
  }
  // synthetic EOS candidate for finished beams (logp forced to 0 at <eos>)
  if (t<KB && sfin[t]){
    float v = sscore[t];
    int flat = t*VV + EOSTOK;
    unsigned long long k = ((unsigned long long)ordkey(v)<<32) | (unsigned)(~(unsigned)flat);
    if (k > list[9]){
      list[9]=k;
      for (int j=8;j>=0;j--){
        if (list[j] < list[j+1]){ unsigned long long tmp=list[j]; list[j]=list[j+1]; list[j+1]=tmp; }
        else break;
      }
    }
  }
  #pragma unroll
  for (int j=0;j<10;j++) skeys[t*10+j]=list[j];
  __syncthreads();
  for (int j=0;j<10;j++){
    unsigned long long m=0ull;
    #pragma unroll
    for (int q=0;q<10;q++){ unsigned long long k=skeys[t*10+q]; if (k>m) m=k; }
    for (int o=16;o>0;o>>=1){
      unsigned long long ok = __shfl_down_sync(0xffffffffu, m, o);
      if (ok>m) m=ok;
    }
    if (lane==0) wmax[wid]=m;
    __syncthreads();
    if (t==0){
      unsigned long long w=wmax[0];
      for (int q=1;q<8;q++) if (wmax[q]>w) w=wmax[q];
      swin=w; topk[j]=w;
    }
    __syncthreads();
    unsigned long long win = swin;
    #pragma unroll
    for (int q=0;q<10;q++) if (skeys[t*10+q]==win) skeys[t*10+q]=0ull;
    __syncthreads();
  }
  if (t<KB){
    unsigned long long k = topk[t];
    sval[t] = unordkey((unsigned)(k>>32));
    int flat = (int)(~(unsigned)(k & 0xffffffffu));
    spb[t]  = flat / VV;
    stok[t] = flat % VV;
  }
  for (int i=t;i<KB*SEQW;i+=256) sseq[i] = g_seqs[i];
  __syncthreads();
  for (int i=t;i<KB*H1D;i+=256){
    int nb=i>>7, u=i&127;
    g_h1[i]=g_h1n[spb[nb]*H1D+u];
    g_c1[i]=g_c1n[spb[nb]*H1D+u];
  }
  for (int i=t;i<KB*H2D;i+=256){
    int nb=i>>6, u=i&63;
    g_h2[i]=g_h2n[spb[nb]*H2D+u];
    g_c2[i]=g_c2n[spb[nb]*H2D+u];
    g_ctx[i]=g_ctxn[spb[nb]*QQ+u];
  }
  for (int i=t;i<KB*SEQW;i+=256){
    int nb=i/SEQW, cc=i%SEQW;
    g_seqs[i] = sseq[spb[nb]*SEQW+cc];
  }
  __syncthreads();
  if (t<KB){
    g_seqs[t*SEQW + step + 1] = stok[t];
    g_prev[t]   = stok[t];
    g_scores[t] = sval[t];
    g_fin[t]    = sfin[spb[t]] | (stok[t]==EOSTOK);
  }
}

// ---------------- finalize: seqs (as float), scores, norm_scores ----------------
__global__ void finalize_kernel(float* __restrict__ out){
  __shared__ float snorm[KB];
  int t = threadIdx.x;
  if (t<KB){
    int first=-1;
    for (int c=1;c<=MAXLEN;c++){
      if (g_seqs[t*SEQW+c]==EOSTOK){ first=c-1; break; }
    }
    float len = (first>=0) ? (float)(first+2) : (float)(MAXLEN+2);
    snorm[t] = (float)((double)g_scores[t] / pow((double)len, 1.2));
  }
  __syncthreads();
  for (int i=t;i<KB*SEQW;i+=256) out[i] = (float)g_seqs[i];
  if (t<KB){
    out[KB*SEQW + t]       = g_scores[t];
    out[KB*SEQW + KB + t]  = snorm[t];
  }
}

extern "C" void kernel_launch(void* const* d_in, const int* in_sizes, int n_in,
                              void* d_out, int out_size){
  const float* enc_key = (const float*)d_in[0];
  const float* enc_val = (const float*)d_in[1];
  const float* mask    = (const float*)d_in[2];
  const float* emb     = (const float*)d_in[3];
  const float* Wih1    = (const float*)d_in[4];
  const float* Whh1    = (const float*)d_in[5];
  const float* bih1    = (const float*)d_in[6];
  const float* bhh1    = (const float*)d_in[7];
  const float* Wih2    = (const float*)d_in[8];
  const float* Whh2    = (const float*)d_in[9];
  const float* bih2    = (const float*)d_in[10];
  const float* bhh2    = (const float*)d_in[11];
  const float* Wq      = (const float*)d_in[12];
  const float* bq      = (const float*)d_in[13];
  const float* Wc      = (const float*)d_in[14];
  const float* bc      = (const float*)d_in[15];

  init_kernel<<<1,256>>>();
  for (int step=0; step<MAXLEN; step++){
    lstm1_kernel<<<H1D,128>>>(emb, Wih1, Whh1, bih1, bhh1);
    lstm2_kernel<<<H2D,128>>>(Wih2, Whh2, bih2, bhh2);
    attn_kernel<<<KB*NCHUNK,256>>>(enc_key, enc_val, mask, Wq, bq);
    logits_kernel<<<NBL,256>>>(Wc, bc);
    select_kernel<<<1,256>>>(step);
  }
  finalize_kernel<<<1,256>>>((float*)d_out);
}

// round 7
// speedup vs baseline: 2.2245x; 1.8904x over previous
#include <cuda_runtime.h>
#include <math.h>

#define KB 10
#define VV 50257
#define EE 128
#define H1D 128
#define H2D 64
#define QQ 64
#define TENC 2048
#define MAXLEN 30
#define SOSTOK 1
#define EOSTOK 2
#define NBL 99
#define RPB 512            // 99*512 = 50688 >= 50257 (2 rows/thread, 256 threads)
#define NCHUNK 16
#define CHUNK 128
#define SEQW (MAXLEN + 1)  // 31
#define TPB 12             // candidates kept per (beam, block)

// ---------------- persistent device state ----------------
__device__ float g_h1[KB*H1D], g_c1[KB*H1D], g_h2[KB*H2D], g_c2[KB*H2D], g_ctx[KB*QQ];
__device__ float g_h1n[KB*H1D], g_c1n[KB*H1D], g_h2n[KB*H2D], g_c2n[KB*H2D], g_ctxn[KB*QQ];
__device__ float g_scores[KB];
__device__ int   g_prev[KB], g_fin[KB], g_seqs[KB*SEQW];
__device__ float g_attM[KB*NCHUNK], g_attA[KB*NCHUNK], g_attB[KB*NCHUNK];
__device__ float g_attC[KB*NCHUNK*QQ];
__device__ __align__(16) float g_xbuf[KB*128];
__device__ double g_sump[NBL*KB];
__device__ float g_cand_val[NBL*KB*TPB];
__device__ int   g_cand_idx[NBL*KB*TPB];

// order-preserving float -> u32 key (larger key == larger float)
__device__ __forceinline__ unsigned ordkey(float f){
  unsigned u = __float_as_uint(f);
  return (u & 0x80000000u) ? ~u : (u | 0x80000000u);
}
__device__ __forceinline__ float unordkey(unsigned k){
  unsigned u = (k & 0x80000000u) ? (k & 0x7FFFFFFFu) : ~k;
  return __uint_as_float(u);
}
// packed 2xfp32 FMA: d.lo += a.lo*b.lo ; d.hi += a.hi*b.hi
__device__ __forceinline__ void ffma2(unsigned long long& d, unsigned long long a, unsigned long long b){
  asm("fma.rn.f32x2 %0, %1, %2, %0;" : "+l"(d) : "l"(a), "l"(b));
}
// compensated fp32 FMA accumulate: (s,c) += a*b with TwoProd error capture.
// true value ~= s - c, accurate to ~1e-7 relative (double-equivalent for our grid).
__device__ __forceinline__ void kfma(float& s, float& c, float a, float b){
  float p  = __fmul_rn(a, b);
  float e  = __fmaf_rn(a, b, -p);   // exact product error
  float y  = p - c;
  float t2 = s + y;
  c = (t2 - s) - y;
  s = t2;
  c -= e;
}

// ---------------- init ----------------
__global__ void init_kernel(){
  int t = threadIdx.x;
  for (int i=t;i<KB*H1D;i+=256){ g_h1[i]=0.f; g_c1[i]=0.f; }
  for (int i=t;i<KB*H2D;i+=256){ g_h2[i]=0.f; g_c2[i]=0.f; }
  for (int i=t;i<KB*QQ;i+=256)  g_ctx[i]=0.f;
  for (int i=t;i<KB*SEQW;i+=256) g_seqs[i]=SOSTOK;
  if (t<KB){ g_scores[t]=0.f; g_prev[t]=SOSTOK; g_fin[t]=0; }
}

// ---------------- LSTM1: grid(128), block(128) ----------------
__global__ void lstm1_kernel(const float* __restrict__ emb, const float* __restrict__ Wih,
                             const float* __restrict__ Whh, const float* __restrict__ bih,
                             const float* __restrict__ bhh){
  __shared__ float sx[KB*192], sh[KB*H1D];
  __shared__ double sg[4*KB], snl[4*KB];
  int t = threadIdx.x, n = blockIdx.x;
  for (int i=t;i<KB*192;i+=128){
    int b=i/192, j=i%192;
    sx[i] = (j<EE) ? emb[(size_t)g_prev[b]*EE + j] : g_ctx[b*QQ + (j-EE)];
  }
  for (int i=t;i<KB*H1D;i+=128) sh[i] = g_h1[i];
  __syncthreads();
  int g = t>>5, lane = t&31;
  const float* wi = Wih + (size_t)(g*H1D+n)*192;
  const float* wh = Whh + (size_t)(g*H1D+n)*H1D;
  float s[KB], c[KB];
  #pragma unroll
  for (int b=0;b<KB;b++){ s[b]=0.f; c[b]=0.f; }
  for (int j=lane;j<192;j+=32){
    float w = wi[j];
    #pragma unroll
    for (int b=0;b<KB;b++) kfma(s[b], c[b], w, sx[b*192+j]);
  }
  for (int j=lane;j<H1D;j+=32){
    float w = wh[j];
    #pragma unroll
    for (int b=0;b<KB;b++) kfma(s[b], c[b], w, sh[b*H1D+j]);
  }
  double bb = (double)bih[g*H1D+n] + (double)bhh[g*H1D+n];
  #pragma unroll
  for (int b=0;b<KB;b++){
    float ss=s[b], cc=c[b];
    for (int o=16;o>0;o>>=1){
      ss += __shfl_down_sync(0xffffffffu, ss, o);
      cc += __shfl_down_sync(0xffffffffu, cc, o);
    }
    if (lane==0) sg[g*KB+b] = ((double)ss - (double)cc) + bb;
  }
  __syncthreads();
  if (t<4*KB){
    int gg=t/KB;
    double v = sg[t];
    snl[t] = (gg==2) ? tanh(v) : 1.0/(1.0+exp(-v));
  }
  __syncthreads();
  if (t<KB){
    double cd = snl[1*KB+t]*(double)g_c1[t*H1D+n] + snl[0*KB+t]*snl[2*KB+t];
    float cf = (float)cd;
    g_c1n[t*H1D+n] = cf;
    g_h1n[t*H1D+n] = (float)(snl[3*KB+t]*tanh((double)cf));
  }
}

// ---------------- LSTM2: grid(64), block(128) ----------------
__global__ void lstm2_kernel(const float* __restrict__ Wih, const float* __restrict__ Whh,
                             const float* __restrict__ bih, const float* __restrict__ bhh){
  __shared__ float sx[KB*H1D], sh[KB*H2D];
  __shared__ double sg[4*KB], snl[4*KB];
  int t = threadIdx.x, n = blockIdx.x;
  for (int i=t;i<KB*H1D;i+=128) sx[i] = g_h1n[i];
  for (int i=t;i<KB*H2D;i+=128) sh[i] = g_h2[i];
  __syncthreads();
  int g = t>>5, lane = t&31;
  const float* wi = Wih + (size_t)(g*H2D+n)*H1D;
  const float* wh = Whh + (size_t)(g*H2D+n)*H2D;
  float s[KB], c[KB];
  #pragma unroll
  for (int b=0;b<KB;b++){ s[b]=0.f; c[b]=0.f; }
  for (int j=lane;j<H1D;j+=32){
    float w = wi[j];
    #pragma unroll
    for (int b=0;b<KB;b++) kfma(s[b], c[b], w, sx[b*H1D+j]);
  }
  for (int j=lane;j<H2D;j+=32){
    float w = wh[j];
    #pragma unroll
    for (int b=0;b<KB;b++) kfma(s[b], c[b], w, sh[b*H2D+j]);
  }
  double bb = (double)bih[g*H2D+n] + (double)bhh[g*H2D+n];
  #pragma unroll
  for (int b=0;b<KB;b++){
    float ss=s[b], cc=c[b];
    for (int o=16;o>0;o>>=1){
      ss += __shfl_down_sync(0xffffffffu, ss, o);
      cc += __shfl_down_sync(0xffffffffu, cc, o);
    }
    if (lane==0) sg[g*KB+b] = ((double)ss - (double)cc) + bb;
  }
  __syncthreads();
  if (t<4*KB){
    int gg=t/KB;
    double v = sg[t];
    snl[t] = (gg==2) ? tanh(v) : 1.0/(1.0+exp(-v));
  }
  __syncthreads();
  if (t<KB){
    double cd = snl[1*KB+t]*(double)g_c2[t*H2D+n] + snl[0*KB+t]*snl[2*KB+t];
    float cf = (float)cd;
    g_c2n[t*H2D+n] = cf;
    g_h2n[t*H2D+n] = (float)(snl[3*KB+t]*tanh((double)cf));
  }
}

// ---------------- attention partials (fp32): grid(KB*16), block(256) ----------------
__global__ void attn_kernel(const float* __restrict__ key, const float* __restrict__ val,
                            const float* __restrict__ mask, const float* __restrict__ Wq,
                            const float* __restrict__ bq){
  __shared__ float h2s[H2D];
  __shared__ float qp[4][QQ];
  __shared__ __align__(16) float qs[QQ];
  __shared__ float ws[CHUNK];
  __shared__ float redm[4];
  __shared__ float redab[4][2];
  __shared__ float cs4[4][QQ];
  int t = threadIdx.x;
  int beam = blockIdx.x >> 4, ch = blockIdx.x & 15;
  if (t<H2D) h2s[t] = g_h2n[beam*H2D+t];
  __syncthreads();
  {
    int qi = t&63, part = t>>6;  // 4 partials of 16 terms
    const float* w = Wq + qi*H2D + part*16;
    float s=0.f, c=0.f;
    #pragma unroll
    for (int j=0;j<16;j++) kfma(s, c, w[j], h2s[part*16+j]);
    qp[part][qi] = s - c;
  }
  __syncthreads();
  if (t<QQ) qs[t] = bq[t] + ((qp[0][t]+qp[1][t])+(qp[2][t]+qp[3][t]));
  __syncthreads();
  int lane = t&31, wid = t>>5;
  int tok = ch*CHUNK + (t&127);
  float e = -1e30f;
  if (t<128){
    const float4* kr = (const float4*)(key + (size_t)tok*QQ);
    const float4* q4 = (const float4*)qs;
    float s0=0,c0=0,s1=0,c1=0,s2=0,c2=0,s3=0,c3=0;
    #pragma unroll
    for (int j=0;j<16;j++){
      float4 kv = kr[j];
      float4 qv = q4[j];
      kfma(s0,c0,qv.x,kv.x);
      kfma(s1,c1,qv.y,kv.y);
      kfma(s2,c2,qv.z,kv.z);
      kfma(s3,c3,qv.w,kv.w);
    }
    e = ((s0-c0)+(s1-c1))+((s2-c2)+(s3-c3));
  }
  float m = e;
  for (int o=16;o>0;o>>=1) m = fmaxf(m, __shfl_down_sync(0xffffffffu, m, o));
  if (lane==0 && wid<4) redm[wid]=m;
  __syncthreads();
  float M = fmaxf(fmaxf(redm[0],redm[1]),fmaxf(redm[2],redm[3]));
  float wexp=0.f, wmask=0.f;
  if (t<128){
    wexp = expf(e-M);
    wmask = wexp*mask[tok];
    ws[t] = wmask;
  }
  float a=wexp, b2=wmask;
  for (int o=16;o>0;o>>=1){
    a  += __shfl_down_sync(0xffffffffu, a, o);
    b2 += __shfl_down_sync(0xffffffffu, b2, o);
  }
  if (lane==0 && wid<4){ redab[wid][0]=a; redab[wid][1]=b2; }
  __syncthreads();
  // ctx partial: 4 groups of 32 tokens, v = t&63
  {
    int v = t&63, grp = t>>6;
    const float* vb = val + (size_t)(ch*CHUNK + grp*32)*QQ + v;
    float s0=0,c0=0,s1=0,c1=0;
    #pragma unroll 4
    for (int tl=0; tl<32; tl+=2){
      kfma(s0,c0, ws[grp*32+tl],   vb[(size_t)tl*QQ]);
      kfma(s1,c1, ws[grp*32+tl+1], vb[(size_t)(tl+1)*QQ]);
    }
    cs4[grp][v] = (s0-c0)+(s1-c1);
  }
  __syncthreads();
  if (t<QQ) g_attC[(beam*NCHUNK+ch)*QQ + t] = (cs4[0][t]+cs4[1][t])+(cs4[2][t]+cs4[3][t]);
  if (t==0){
    g_attM[beam*NCHUNK+ch]=M;
    g_attA[beam*NCHUNK+ch]=(redab[0][0]+redab[1][0])+(redab[2][0]+redab[3][0]);
    g_attB[beam*NCHUNK+ch]=(redab[0][1]+redab[1][1])+(redab[2][1]+redab[3][1]);
  }
}

// ---------------- merge attention partials -> x buffer (once): 1 block, 256 ----------------
__global__ void merge_kernel(){
  __shared__ float sM[KB];
  __shared__ float scf[KB][NCHUNK];
  __shared__ double sA[KB], sB[KB];
  int t = threadIdx.x;
  if (t<KB){
    float M=-1e30f;
    #pragma unroll
    for (int c=0;c<NCHUNK;c++) M = fmaxf(M, g_attM[t*NCHUNK+c]);
    sM[t]=M;
  }
  __syncthreads();
  if (t<KB*NCHUNK){
    int b=t/NCHUNK;
    scf[b][t%NCHUNK] = expf(g_attM[t]-sM[b]);
  }
  __syncthreads();
  if (t<KB){
    double A=0.0, B=0.0;
    #pragma unroll
    for (int c=0;c<NCHUNK;c++){
      A += (double)g_attA[t*NCHUNK+c]*(double)scf[t][c];
      B += (double)g_attB[t*NCHUNK+c]*(double)scf[t][c];
    }
    sA[t]=A; sB[t]=B;
  }
  __syncthreads();
  for (int i=t;i<KB*128;i+=256){
    int b=i>>7, j=i&127;
    float x;
    if (j < H2D) x = g_h2n[b*H2D+j];
    else {
      int v = j - H2D;
      float s=0.f, c=0.f;
      #pragma unroll
      for (int cc=0;cc<NCHUNK;cc++) kfma(s, c, g_attC[(b*NCHUNK+cc)*QQ+v], scf[b][cc]);
      double Cd = (double)s - (double)c;
      x = (float)((Cd/sA[b]) / fmax(sB[b]/sA[b], 2e-30));
      g_ctxn[b*QQ+v] = x;
    }
    g_xbuf[i] = x;
  }
}

// ---------------- logits + sumexp + per-(beam,block) top-12: grid(99), block(256), 2 rows/thread ----------------
__global__ void __launch_bounds__(256) logits_kernel(const float* __restrict__ Wc, const float* __restrict__ bc){
  __shared__ __align__(16) float xs[KB*128];
  __shared__ float lg[KB][RPB];
  __shared__ float wred[8][KB];
  int t = threadIdx.x;
  for (int i=t;i<KB*128;i+=256) xs[i]=g_xbuf[i];
  __syncthreads();
  int v0 = blockIdx.x*RPB + t;
  int v1 = v0 + 256;
  bool ok0 = v0 < VV, ok1 = v1 < VV;
  const ulonglong2* wr0 = (const ulonglong2*)(Wc + (size_t)(ok0?v0:0)*128);
  const ulonglong2* wr1 = (const ulonglong2*)(Wc + (size_t)(ok1?v1:0)*128);
  const ulonglong2* xp = (const ulonglong2*)xs;
  unsigned long long a0[KB], a1[KB];
  #pragma unroll
  for (int b=0;b<KB;b++){ a0[b]=0ull; a1[b]=0ull; }
  #pragma unroll 2
  for (int j=0;j<32;j++){
    ulonglong2 w0 = wr0[j];
    ulonglong2 w1 = wr1[j];
    #pragma unroll
    for (int b=0;b<KB;b++){
      ulonglong2 xv = xp[b*32+j];
      ffma2(a0[b], w0.x, xv.x);
      ffma2(a0[b], w0.y, xv.y);
      ffma2(a1[b], w1.x, xv.x);
      ffma2(a1[b], w1.y, xv.y);
    }
  }
  float bc0 = ok0 ? bc[v0] : 0.f;
  float bc1 = ok1 ? bc[v1] : 0.f;
  float ex[KB];
  #pragma unroll
  for (int b=0;b<KB;b++){
    float lo0 = __uint_as_float((unsigned)(a0[b] & 0xffffffffu));
    float hi0 = __uint_as_float((unsigned)(a0[b] >> 32));
    float lo1 = __uint_as_float((unsigned)(a1[b] & 0xffffffffu));
    float hi1 = __uint_as_float((unsigned)(a1[b] >> 32));
    float l0 = ok0 ? (lo0 + hi0) + bc0 : -1e30f;
    float l1 = ok1 ? (lo1 + hi1) + bc1 : -1e30f;
    lg[b][t]     = l0;
    lg[b][t+256] = l1;
    ex[b] = expf(l0) + expf(l1);   // expf(-1e30) = 0 for OOB
  }
  int wid = t>>5, lane = t&31;
  #pragma unroll
  for (int b=0;b<KB;b++){
    float s = ex[b];
    for (int o=16;o>0;o>>=1) s += __shfl_down_sync(0xffffffffu, s, o);
    if (lane==0) wred[wid][b] = s;
  }
  __syncthreads();
  if (t<KB){
    double s=0.0;
    for (int w=0;w<8;w++) s += (double)wred[w][t];
    g_sump[blockIdx.x*KB+t] = s;
  }
  // per-(beam,block) exact top-12 (warp w handles beams w, w+8)
  for (int bm=wid; bm<KB; bm+=8){
    for (int j=0;j<TPB;j++){
      unsigned long long best=0ull;
      for (int r2=lane; r2<RPB; r2+=32){
        unsigned long long k = ((unsigned long long)ordkey(lg[bm][r2])<<32) | (unsigned)(~(unsigned)r2);
        if (k>best) best=k;
      }
      for (int o=16;o>0;o>>=1){
        unsigned long long ok = __shfl_down_sync(0xffffffffu, best, o);
        if (ok>best) best=ok;
      }
      best = __shfl_sync(0xffffffffu, best, 0);
      int rs = (int)(~(unsigned)(best & 0xffffffffu));
      if (lane==0){
        g_cand_val[(blockIdx.x*KB+bm)*TPB+j] = lg[bm][rs];
        g_cand_idx[(blockIdx.x*KB+bm)*TPB+j] = blockIdx.x*RPB + rs;
        lg[bm][rs] = -1e30f;
      }
      __syncwarp();
    }
  }
}

// ---------------- select top-10 over all candidates + beam gather: 1 block, 256 threads ----------------
__global__ void select_kernel(int step){
  __shared__ float slse[KB], sscore[KB], sval[KB];
  __shared__ int sfin[KB], spb[KB], stok[KB];
  __shared__ double sp[256];
  __shared__ unsigned long long skeys[256*10];
  __shared__ unsigned long long wmax[8];
  __shared__ unsigned long long swin;
  __shared__ unsigned long long topk[KB];
  __shared__ int sseq[KB*SEQW];
  int t = threadIdx.x, lane = t&31, wid = t>>5;
  {
    double s=0.0;
    if (t < 250){
      int b = t/25, part = t%25;
      for (int b2=part; b2<NBL; b2+=25) s += g_sump[b2*KB+b];
    }
    sp[t]=s;
  }
  __syncthreads();
  if (t<KB){
    double s=0.0;
    for (int q=0;q<25;q++) s += sp[t*25+q];
    slse[t] = (float)log(s);
    sscore[t] = g_scores[t];
    sfin[t] = g_fin[t];
  }
  __syncthreads();
  unsigned long long list[10];
  #pragma unroll
  for (int j=0;j<10;j++) list[j]=0ull;
  const int NC = NBL*KB*TPB;
  for (int c=t;c<NC;c+=256){
    int b = (c/TPB)%KB;
    if (sfin[b]) continue;
    if (step==0 && b>0) continue;
    // mirror reference fp32 op order: cand = scores + (logit - lse)
    float logp = g_cand_val[c] - slse[b];
    float v = sscore[b] + logp;
    int flat = b*VV + g_cand_idx[c];
    unsigned long long k = ((unsigned long long)ordkey(v)<<32) | (unsigned)(~(unsigned)flat);
    if (k > list[9]){
      list[9]=k;
      for (int j=8;j>=0;j--){
        if (list[j] < list[j+1]){ unsigned long long tmp=list[j]; list[j]=list[j+1]; list[j+1]=tmp; }
        else break;
      }
    }
  }
  if (t<KB && sfin[t]){
    float v = sscore[t];
    int flat = t*VV + EOSTOK;
    unsigned long long k = ((unsigned long long)ordkey(v)<<32) | (unsigned)(~(unsigned)flat);
    if (k > list[9]){
      list[9]=k;
      for (int j=8;j>=0;j--){
        if (list[j] < list[j+1]){ unsigned long long tmp=list[j]; list[j]=list[j+1]; list[j+1]=tmp; }
        else break;
      }
    }
  }
  #pragma unroll
  for (int j=0;j<10;j++) skeys[t*10+j]=list[j];
  __syncthreads();
  for (int j=0;j<10;j++){
    unsigned long long m=0ull;
    #pragma unroll
    for (int q=0;q<10;q++){ unsigned long long k=skeys[t*10+q]; if (k>m) m=k; }
    for (int o=16;o>0;o>>=1){
      unsigned long long ok = __shfl_down_sync(0xffffffffu, m, o);
      if (ok>m) m=ok;
    }
    if (lane==0) wmax[wid]=m;
    __syncthreads();
    if (t==0){
      unsigned long long w=wmax[0];
      for (int q=1;q<8;q++) if (wmax[q]>w) w=wmax[q];
      swin=w; topk[j]=w;
    }
    __syncthreads();
    unsigned long long win = swin;
    #pragma unroll
    for (int q=0;q<10;q++) if (skeys[t*10+q]==win) skeys[t*10+q]=0ull;
    __syncthreads();
  }
  if (t<KB){
    unsigned long long k = topk[t];
    sval[t] = unordkey((unsigned)(k>>32));
    int flat = (int)(~(unsigned)(k & 0xffffffffu));
    spb[t]  = flat / VV;
    stok[t] = flat % VV;
  }
  for (int i=t;i<KB*SEQW;i+=256) sseq[i] = g_seqs[i];
  __syncthreads();
  for (int i=t;i<KB*H1D;i+=256){
    int nb=i>>7, u=i&127;
    g_h1[i]=g_h1n[spb[nb]*H1D+u];
    g_c1[i]=g_c1n[spb[nb]*H1D+u];
  }
  for (int i=t;i<KB*H2D;i+=256){
    int nb=i>>6, u=i&63;
    g_h2[i]=g_h2n[spb[nb]*H2D+u];
    g_c2[i]=g_c2n[spb[nb]*H2D+u];
    g_ctx[i]=g_ctxn[spb[nb]*QQ+u];
  }
  for (int i=t;i<KB*SEQW;i+=256){
    int nb=i/SEQW, cc=i%SEQW;
    g_seqs[i] = sseq[spb[nb]*SEQW+cc];
  }
  __syncthreads();
  if (t<KB){
    g_seqs[t*SEQW + step + 1] = stok[t];
    g_prev[t]   = stok[t];
    g_scores[t] = sval[t];
    g_fin[t]    = sfin[spb[t]] | (stok[t]==EOSTOK);
  }
}

// ---------------- finalize: seqs (as float), scores, norm_scores ----------------
__global__ void finalize_kernel(float* __restrict__ out){
  __shared__ float snorm[KB];
  int t = threadIdx.x;
  if (t<KB){
    int first=-1;
    for (int c=1;c<=MAXLEN;c++){
      if (g_seqs[t*SEQW+c]==EOSTOK){ first=c-1; break; }
    }
    float len = (first>=0) ? (float)(first+2) : (float)(MAXLEN+2);
    snorm[t] = (float)((double)g_scores[t] / pow((double)len, 1.2));
  }
  __syncthreads();
  for (int i=t;i<KB*SEQW;i+=256) out[i] = (float)g_seqs[i];
  if (t<KB){
    out[KB*SEQW + t]       = g_scores[t];
    out[KB*SEQW + KB + t]  = snorm[t];
  }
}

extern "C" void kernel_launch(void* const* d_in, const int* in_sizes, int n_in,
                              void* d_out, int out_size){
  const float* enc_key = (const float*)d_in[0];
  const float* enc_val = (const float*)d_in[1];
  const float* mask    = (const float*)d_in[2];
  const float* emb     = (const float*)d_in[3];
  const float* Wih1    = (const float*)d_in[4];
  const float* Whh1    = (const float*)d_in[5];
  const float* bih1    = (const float*)d_in[6];
  const float* bhh1    = (const float*)d_in[7];
  const float* Wih2    = (const float*)d_in[8];
  const float* Whh2    = (const float*)d_in[9];
  const float* bih2    = (const float*)d_in[10];
  const float* bhh2    = (const float*)d_in[11];
  const float* Wq      = (const float*)d_in[12];
  const float* bq      = (const float*)d_in[13];
  const float* Wc      = (const float*)d_in[14];
  const float* bc      = (const float*)d_in[15];

  init_kernel<<<1,256>>>();
  for (int step=0; step<MAXLEN; step++){
    lstm1_kernel<<<H1D,128>>>(emb, Wih1, Whh1, bih1, bhh1);
    lstm2_kernel<<<H2D,128>>>(Wih2, Whh2, bih2, bhh2);
    attn_kernel<<<KB*NCHUNK,256>>>(enc_key, enc_val, mask, Wq, bq);
    merge_kernel<<<1,256>>>();
    logits_kernel<<<NBL,256>>>(Wc, bc);
    select_kernel<<<1,256>>>(step);
  }
  finalize_kernel<<<1,256>>>((float*)d_out);
}